// round 14
// baseline (speedup 1.0000x reference)
#include <cuda_runtime.h>

#define IMG    512
#define OUTD   502
#define NIMG   96
#define TILE_W 86
#define VCOLS  96
#define STRIPH 32
#define BROWS  16
#define GBX    6
#define GBY    16
#define NBLK   (GBX * GBY * NIMG)   // 9216
#define SROW   104                   // bank-conflict-free for u64 planes (8y+11cg mod 16 bijective)
#define G      11

// k_flags exact partition
#define FB     3072
#define FT     256
#define FITER  8

// Gaussian(sigma=1.5, K=11) normalized weights
#define W0 0.00102839f
#define W1 0.00759864f
#define W2 0.03600077f
#define W3 0.10936070f
#define W4 0.21300553f
#define W5 0.26601172f

typedef unsigned long long u64;

#define PACK2(out, lo, hi) asm("mov.b64 %0, {%1, %2};" : "=l"(out) : "f"(lo), "f"(hi))
#define UNPACK2(lo, hi, in) asm("mov.b64 {%0, %1}, %2;" : "=f"(lo), "=f"(hi) : "l"(in))
#define FMA2(d, a, b, c) asm("fma.rn.f32x2 %0, %1, %2, %3;" : "=l"(d) : "l"(a), "l"(b), "l"(c))
#define MUL2(d, a, b)    asm("mul.rn.f32x2 %0, %1, %2;" : "=l"(d) : "l"(a), "l"(b))

#define WIDX(k) ((k) < 6 ? (k) : 10 - (k))

__device__ int      g_flags[2] = {0, 0};
__device__ unsigned g_count    = 0u;
__device__ float    g_partials[NBLK];

__global__ __launch_bounds__(FT)
void k_flags(const float4* __restrict__ x) {
    const int base = blockIdx.x * FT + threadIdx.x;
    bool f1 = false, f2 = false;
#pragma unroll
    for (int i = 0; i < FITER; i++) {
        float4 v = x[base + i * (FB * FT)];
        f1 |= (v.x > 128.0f) | (v.y > 128.0f) | (v.z > 128.0f) | (v.w > 128.0f);
        f2 |= (v.x < -0.5f) | (v.y < -0.5f) | (v.z < -0.5f) | (v.w < -0.5f);
    }
    unsigned m1 = __ballot_sync(0xffffffffu, f1);
    unsigned m2 = __ballot_sync(0xffffffffu, f2);
    if ((threadIdx.x & 31) == 0) {
        if (m1) atomicOr(&g_flags[0], 1);
        if (m2) atomicOr(&g_flags[1], 1);
    }
}

// one 16-input-row phase-1 chunk; JS = first input row (strip-relative), RG = row guard
template <int JS, bool RG>
__device__ __forceinline__ void p1chunk(const float* __restrict__ p1,
                                        const float* __restrict__ p2,
                                        int sy, int gx, bool colok,
                                        const u64* w2,
                                        u64 (*s01)[SROW], u64 (*sq)[SROW],
                                        u64* acc01, u64* accq, int tid) {
#pragma unroll
    for (int jj = 0; jj < 16; jj++) {
        const int j = JS + jj;
        const int yin = sy + j;
        float a = 0.0f, b = 0.0f;
        if (colok && (!RG || yin < IMG)) {
            a = p1[yin * IMG + gx];
            b = p2[yin * IMG + gx];
        }
        const float ab   = a * b;
        const float aabb = fmaf(a, a, b * b);
        u64 vab, vq;
        PACK2(vab, a, b);
        PACK2(vq, aabb, ab);

        if (j <= STRIPH - 1) {                 // new output row r=j starts (first tap, w[0])
            MUL2(acc01[j % 11], vab, w2[0]);
            MUL2(accq[j % 11],  vq,  w2[0]);
        }
#pragma unroll
        for (int k = 1; k <= 10; k++) {
            const int r = j - k;
            if (r >= 0 && r <= STRIPH - 1) {
                const int m = r % 11;          // static after unroll
                FMA2(acc01[m], vab, w2[WIDX(k)], acc01[m]);
                FMA2(accq[m],  vq,  w2[WIDX(k)], accq[m]);
            }
        }
        {                                      // output row j-10 completes now
            const int r = j - 10;
            s01[r & 15][tid] = acc01[r % 11];
            sq [r & 15][tid] = accq[r % 11];
        }
    }
}

__global__ __launch_bounds__(128, 5)
void k_ssim(const float* __restrict__ img1, const float* __restrict__ img2,
            float* __restrict__ out) {
    __shared__ u64   s01[BROWS][SROW];
    __shared__ u64   sq [BROWS][SROW];
    __shared__ float warpsum[4];
    __shared__ int   s_last;
    __shared__ double red[4];

    u64 w2[6];
    {
        const float wv[6] = {W0, W1, W2, W3, W4, W5};
#pragma unroll
        for (int k = 0; k < 6; k++) PACK2(w2[k], wv[k], wv[k]);
    }

    const int tid = threadIdx.x;
    const int bx = blockIdx.x, by = blockIdx.y, z = blockIdx.z;
    const float* p1 = img1 + (size_t)z * IMG * IMG;
    const float* p2 = img2 + (size_t)z * IMG * IMG;
    const int sy = by * STRIPH;

    const int gx = bx * TILE_W + tid;
    const bool colok = (tid < VCOLS) && (gx < IMG);

    u64 acc01[11], accq[11];

    // ---------------- Warmup: input rows 0..9 (always in-bounds: sy+9 <= 489) -------------
    if (tid < VCOLS) {
#pragma unroll
        for (int j = 0; j < 10; j++) {
            const int yin = sy + j;
            float a = 0.0f, b = 0.0f;
            if (colok) {
                a = p1[yin * IMG + gx];
                b = p2[yin * IMG + gx];
            }
            const float ab   = a * b;
            const float aabb = fmaf(a, a, b * b);
            u64 vab, vq;
            PACK2(vab, a, b);
            PACK2(vq, aabb, ab);
            MUL2(acc01[j % 11], vab, w2[0]);
            MUL2(accq[j % 11],  vq,  w2[0]);
#pragma unroll
            for (int k = 1; k <= 10; k++) {
                if (k <= j) {
                    const int m = (j - k) % 11;
                    FMA2(acc01[m], vab, w2[WIDX(k)], acc01[m]);
                    FMA2(accq[m],  vq,  w2[WIDX(k)], accq[m]);
                }
            }
        }
    }

    const float maxv = g_flags[0] ? 255.0f : 1.0f;
    const float minv = g_flags[1] ? -1.0f : 0.0f;
    const float L  = maxv - minv;
    const float C1 = (0.01f * L) * (0.01f * L);
    const float C2 = (0.03f * L) * (0.03f * L);

    const int y  = tid >> 3;
    const int cg = tid & 7;
    const int xs = cg * G;
    const int xlim = min(TILE_W, OUTD - bx * TILE_W);

    float lsum = 0.0f;

    // ================= chunk 0: inputs 10..25, outputs 0..15 =================
    if (tid < VCOLS)
        p1chunk<10, false>(p1, p2, sy, gx, colok, w2, s01, sq, acc01, accq, tid);
    __syncthreads();

#pragma unroll 1
    for (int c = 0; c < 2; c++) {
        // ---- Phase 2 on buffer rows 0..15 (outputs sy + c*16 + y) ----
        u64 o01[G], oq[G];
#pragma unroll
        for (int s = 0; s < G; s++) { o01[s] = 0ull; oq[s] = 0ull; }
        {
            const u64* r01 = &s01[y][xs];
#pragma unroll
            for (int i = 0; i < 21; i++) {
                const u64 v = r01[i];
#pragma unroll
                for (int s = 0; s < G; s++) {
                    const int k = i - s;
                    if (k >= 0 && k < 11) FMA2(o01[s], v, w2[WIDX(k)], o01[s]);
                }
            }
        }
        {
            const u64* rq = &sq[y][xs];
#pragma unroll
            for (int i = 0; i < 21; i++) {
                const u64 v = rq[i];
#pragma unroll
                for (int s = 0; s < G; s++) {
                    const int k = i - s;
                    if (k >= 0 && k < 11) FMA2(oq[s], v, w2[WIDX(k)], oq[s]);
                }
            }
        }

        const int gy = sy + c * 16 + y;
        if (gy < OUTD) {
#pragma unroll
            for (int s = 0; s < G; s++) {
                const int x = xs + s;
                if (x < xlim) {
                    float mu1, mu2, spp, sab;
                    UNPACK2(mu1, mu2, o01[s]);
                    UNPACK2(spp, sab, oq[s]);
                    const float mu1s = mu1 * mu1, mu2s = mu2 * mu2, mu12 = mu1 * mu2;
                    const float sigsum = spp - mu1s - mu2s;
                    const float sig12  = sab - mu12;
                    const float num = (2.0f * mu12 + C1) * (2.0f * sig12 + C2);
                    const float den = (mu1s + mu2s + C1) * (sigsum + C2);
                    lsum += __fdividef(num, den);
                }
            }
        }

        if (c == 0) {
            __syncthreads();   // phase-2 reads done before chunk-1 overwrites buffer
            // ====== chunk 1: inputs 26..41, outputs 16..31 (carry already in registers) ======
            if (tid < VCOLS) {
                if (sy + 41 < IMG)
                    p1chunk<26, false>(p1, p2, sy, gx, colok, w2, s01, sq, acc01, accq, tid);
                else
                    p1chunk<26, true >(p1, p2, sy, gx, colok, w2, s01, sq, acc01, accq, tid);
            }
            __syncthreads();
        }
    }

    // ---------------- block reduction ----------------
#pragma unroll
    for (int off = 16; off > 0; off >>= 1)
        lsum += __shfl_down_sync(0xffffffffu, lsum, off);

    if ((tid & 31) == 0) warpsum[tid >> 5] = lsum;
    __syncthreads();

    const int bid = bx + GBX * (by + GBY * z);
    if (tid == 0) {
        g_partials[bid] = warpsum[0] + warpsum[1] + warpsum[2] + warpsum[3];
        __threadfence();
        unsigned v = atomicAdd(&g_count, 1u);
        s_last = (v == NBLK - 1) ? 1 : 0;
    }
    __syncthreads();

    // ---------------- last block: final reduction + state reset ----------------
    if (s_last) {
        double s = 0.0;
        const int per = NBLK / 128;  // 72
#pragma unroll 4
        for (int i = 0; i < per; i++)
            s += (double)__ldcg(&g_partials[tid * per + i]);
#pragma unroll
        for (int off = 16; off > 0; off >>= 1)
            s += __shfl_down_sync(0xffffffffu, s, off);
        if ((tid & 31) == 0) red[tid >> 5] = s;
        __syncthreads();
        if (tid == 0) {
            const double cnt = (double)NIMG * OUTD * OUTD;
            out[0] = (float)(1.0 - (red[0] + red[1] + red[2] + red[3]) / cnt);
            g_flags[0] = 0;
            g_flags[1] = 0;
            g_count    = 0u;
        }
    }
}

extern "C" void kernel_launch(void* const* d_in, const int* in_sizes, int n_in,
                              void* d_out, int out_size) {
    const float* img1 = (const float*)d_in[0];
    const float* img2 = (const float*)d_in[1];
    float* out = (float*)d_out;

    k_flags<<<FB, FT>>>((const float4*)img1);
    dim3 grid(GBX, GBY, NIMG);
    k_ssim<<<grid, 128>>>(img1, img2, out);
}